// round 5
// baseline (speedup 1.0000x reference)
#include <cuda_runtime.h>
#include <math.h>

// FeedForwardQuantum fused v5:
//   out = cos(relu(x@W1 + b1) + theta) @ W2 + b2
// GEMM1: thread = (g 0..31, qh 0..1, h 0..3): 4 rows (g+32r) x 8 q x 4d-slice
//   per 16d chunk: 4 x-LDS + 8 w-LDS(broadcast) : 64 FFMA2, 32 indep chains.
// x double-buffered in smem (stride 20, conflict-free), register prefetch.
// 4-way h-combine via 2-plane tree. GEMM2: W2 in regs, 4-row unroll.

#define DDIM 1024
#define QDIM 16
#define ROWS 128
#define NTH 256
#define CHD 16
#define NCH 64
#define BSTR 20
#define PSTR 17
#define ZSTR 36

typedef unsigned long long u64;

__device__ __forceinline__ void ffma2(u64 &d, u64 a, u64 b) {
    asm("fma.rn.f32x2 %0, %1, %2, %0;" : "+l"(d) : "l"(a), "l"(b));
}
__device__ __forceinline__ float2 unpk(u64 v) {
    float2 f;
    asm("mov.b64 {%0,%1}, %2;" : "=f"(f.x), "=f"(f.y) : "l"(v));
    return f;
}
__device__ __forceinline__ u64 pk(float x, float y) {
    u64 v;
    asm("mov.b64 %0, {%1,%2};" : "=l"(v) : "f"(x), "f"(y));
    return v;
}

__global__ void __launch_bounds__(NTH, 2)
ffq_v5(const float* __restrict__ x, const float* __restrict__ W1,
       const float* __restrict__ b1, const float* __restrict__ theta,
       const float* __restrict__ W2, const float* __restrict__ b2,
       float* __restrict__ out, int nRows)
{
    extern __shared__ float sm[];
    float* w1p  = sm;                      // 16384: pair-interleaved W1
    float* buf0 = w1p + DDIM * QDIM;       // 128*20 = 2560
    float* buf1 = buf0 + ROWS * BSTR;      // 2560
    float* zar  = buf1 + ROWS * BSTR;      // 128*36 = 4608 (z duplicated)
    float* b1s  = zar + ROWS * ZSTR;       // 16
    float* ths  = b1s + QDIM;              // 16

    const int tid  = threadIdx.x;
    const int row0 = blockIdx.x * ROWS;

    // ---- stage W1 pair-interleaved: w1p[b*32 + 2q + p] = W1[(2b+p)*16+q] ----
    for (int o = tid; o < DDIM * QDIM; o += NTH) {
        int b = o >> 5, rr = o & 31, q = rr >> 1, pp = rr & 1;
        w1p[o] = W1[(2 * b + pp) * QDIM + q];
    }
    if (tid < QDIM) { b1s[tid] = b1[tid]; ths[tid] = theta[tid]; }

    const int g  = tid & 31;               // row group: rows g+32r, r=0..3
    const int qh = (tid >> 5) & 1;         // q half
    const int h  = tid >> 6;               // d quarter (0..3)

    u64 acc[32];                           // [r 0..3][j 0..7]
#pragma unroll
    for (int i = 0; i < 32; i++) acc[i] = 0ULL;

    // staging: thread owns 2 float4 per 16d chunk: rows srow, srow+64
    const int srow  = tid >> 2;
    const int soff  = (tid & 3) * 4;
    int gr_a = row0 + srow;      if (gr_a >= nRows) gr_a = nRows - 1;
    int gr_b = row0 + srow + 64; if (gr_b >= nRows) gr_b = nRows - 1;
    const float* gpa = x + (size_t)gr_a * DDIM + soff;
    const float* gpb = x + (size_t)gr_b * DDIM + soff;

    float4 pa = *reinterpret_cast<const float4*>(gpa);
    float4 pb = *reinterpret_cast<const float4*>(gpb);
    *reinterpret_cast<float4*>(buf0 + srow * BSTR + soff)        = pa;
    *reinterpret_cast<float4*>(buf0 + (srow + 64) * BSTR + soff) = pb;
    __syncthreads();

    for (int ch = 0; ch < NCH; ch++) {
        float* cb = (ch & 1) ? buf1 : buf0;
        float* nb = (ch & 1) ? buf0 : buf1;

        if (ch + 1 < NCH) {
            int dd = (ch + 1) * CHD;
            pa = *reinterpret_cast<const float4*>(gpa + dd);
            pb = *reinterpret_cast<const float4*>(gpb + dd);
        }

        // x for 4 rows, this thread's 4d slice
        const float* xb = cb + 4 * h;
        ulonglong2 x0 = *reinterpret_cast<const ulonglong2*>(xb + (g)      * BSTR);
        ulonglong2 x1 = *reinterpret_cast<const ulonglong2*>(xb + (g + 32) * BSTR);
        ulonglong2 x2 = *reinterpret_cast<const ulonglong2*>(xb + (g + 64) * BSTR);
        ulonglong2 x3 = *reinterpret_cast<const ulonglong2*>(xb + (g + 96) * BSTR);

        const float* wp = w1p + (ch * 8 + 2 * h) * 32 + 16 * qh;
        // d-pair block 0 (uses x*.x)
#pragma unroll
        for (int m = 0; m < 4; m++) {
            ulonglong2 w = *reinterpret_cast<const ulonglong2*>(wp + 4 * m);
            ffma2(acc[2 * m],      x0.x, w.x);  ffma2(acc[2 * m + 1],  x0.x, w.y);
            ffma2(acc[8 + 2 * m],  x1.x, w.x);  ffma2(acc[9 + 2 * m],  x1.x, w.y);
            ffma2(acc[16 + 2 * m], x2.x, w.x);  ffma2(acc[17 + 2 * m], x2.x, w.y);
            ffma2(acc[24 + 2 * m], x3.x, w.x);  ffma2(acc[25 + 2 * m], x3.x, w.y);
        }
        // d-pair block 1 (uses x*.y)
#pragma unroll
        for (int m = 0; m < 4; m++) {
            ulonglong2 w = *reinterpret_cast<const ulonglong2*>(wp + 32 + 4 * m);
            ffma2(acc[2 * m],      x0.y, w.x);  ffma2(acc[2 * m + 1],  x0.y, w.y);
            ffma2(acc[8 + 2 * m],  x1.y, w.x);  ffma2(acc[9 + 2 * m],  x1.y, w.y);
            ffma2(acc[16 + 2 * m], x2.y, w.x);  ffma2(acc[17 + 2 * m], x2.y, w.y);
            ffma2(acc[24 + 2 * m], x3.y, w.x);  ffma2(acc[25 + 2 * m], x3.y, w.y);
        }

        if (ch + 1 < NCH) {
            *reinterpret_cast<float4*>(nb + srow * BSTR + soff)        = pa;
            *reinterpret_cast<float4*>(nb + (srow + 64) * BSTR + soff) = pb;
        }
        __syncthreads();
    }

    // ---- 4-way h combine (2-plane tree), activation, z-dup into zar ----
    float hv[32];
#pragma unroll
    for (int i = 0; i < 32; i++) {
        float2 a = unpk(acc[i]);
        hv[i] = a.x + a.y;
    }
    // step 1: h=1 -> plane buf0, h=3 -> plane buf1
    if (h == 1 || h == 3) {
        float* pl = (h == 1) ? buf0 : buf1;
#pragma unroll
        for (int r = 0; r < 4; r++)
#pragma unroll
            for (int j = 0; j < 8; j++)
                pl[(g + 32 * r) * PSTR + 8 * qh + j] = hv[8 * r + j];
    }
    __syncthreads();
    // step 2: h=0 adds plane0; h=2 adds plane1 then writes sum to plane1
    if (h == 0) {
#pragma unroll
        for (int r = 0; r < 4; r++)
#pragma unroll
            for (int j = 0; j < 8; j++)
                hv[8 * r + j] += buf0[(g + 32 * r) * PSTR + 8 * qh + j];
    } else if (h == 2) {
#pragma unroll
        for (int r = 0; r < 4; r++)
#pragma unroll
            for (int j = 0; j < 8; j++) {
                float s = hv[8 * r + j] + buf1[(g + 32 * r) * PSTR + 8 * qh + j];
                buf1[(g + 32 * r) * PSTR + 8 * qh + j] = s;
            }
    }
    __syncthreads();
    // step 3: h=0 final sum + activation -> zar (duplicated pairs)
    if (h == 0) {
#pragma unroll
        for (int r = 0; r < 4; r++) {
            int row = g + 32 * r;
#pragma unroll
            for (int j = 0; j < 8; j++) {
                int q = 8 * qh + j;
                float v = hv[8 * r + j] + buf1[row * PSTR + q] + b1s[q];
                v = fmaxf(v, 0.0f) + ths[q];
                float z = __cosf(v);
                zar[row * ZSTR + 2 * q]     = z;
                zar[row * ZSTR + 2 * q + 1] = z;
            }
        }
    }
    __syncthreads();

    // ---- GEMM2: W2 in regs, z broadcast LDS, 4-row unroll, STG.128 ----
    const int dcol = 4 * tid;
    ulonglong2 w2r[QDIM];
#pragma unroll
    for (int q = 0; q < QDIM; q++)
        w2r[q] = *reinterpret_cast<const ulonglong2*>(W2 + q * DDIM + dcol);

    float4 b2v = *reinterpret_cast<const float4*>(b2 + dcol);
    const u64 b2p0 = pk(b2v.x, b2v.y);
    const u64 b2p1 = pk(b2v.z, b2v.w);

    for (int rr = 0; rr < ROWS; rr += 4) {
        u64 a0 = b2p0, a1 = b2p1, c0 = b2p0, c1 = b2p1;
        u64 e0 = b2p0, e1 = b2p1, f0 = b2p0, f1 = b2p1;
        const float* z0 = zar + rr * ZSTR;
        const float* z1 = z0 + ZSTR;
        const float* z2 = z1 + ZSTR;
        const float* z3 = z2 + ZSTR;
#pragma unroll
        for (int m = 0; m < 8; m++) {
            ulonglong2 zd0 = *reinterpret_cast<const ulonglong2*>(z0 + 4 * m);
            ulonglong2 zd1 = *reinterpret_cast<const ulonglong2*>(z1 + 4 * m);
            ulonglong2 zd2 = *reinterpret_cast<const ulonglong2*>(z2 + 4 * m);
            ulonglong2 zd3 = *reinterpret_cast<const ulonglong2*>(z3 + 4 * m);
            ffma2(a0, zd0.x, w2r[2 * m].x);  ffma2(a1, zd0.x, w2r[2 * m].y);
            ffma2(a0, zd0.y, w2r[2 * m + 1].x);  ffma2(a1, zd0.y, w2r[2 * m + 1].y);
            ffma2(c0, zd1.x, w2r[2 * m].x);  ffma2(c1, zd1.x, w2r[2 * m].y);
            ffma2(c0, zd1.y, w2r[2 * m + 1].x);  ffma2(c1, zd1.y, w2r[2 * m + 1].y);
            ffma2(e0, zd2.x, w2r[2 * m].x);  ffma2(e1, zd2.x, w2r[2 * m].y);
            ffma2(e0, zd2.y, w2r[2 * m + 1].x);  ffma2(e1, zd2.y, w2r[2 * m + 1].y);
            ffma2(f0, zd3.x, w2r[2 * m].x);  ffma2(f1, zd3.x, w2r[2 * m].y);
            ffma2(f0, zd3.y, w2r[2 * m + 1].x);  ffma2(f1, zd3.y, w2r[2 * m + 1].y);
        }
        int gr = row0 + rr;
        float2 lo, hi;
        if (gr < nRows) {
            lo = unpk(a0); hi = unpk(a1);
            *reinterpret_cast<float4*>(out + (size_t)gr * DDIM + dcol) =
                make_float4(lo.x, lo.y, hi.x, hi.y);
        }
        if (gr + 1 < nRows) {
            lo = unpk(c0); hi = unpk(c1);
            *reinterpret_cast<float4*>(out + (size_t)(gr + 1) * DDIM + dcol) =
                make_float4(lo.x, lo.y, hi.x, hi.y);
        }
        if (gr + 2 < nRows) {
            lo = unpk(e0); hi = unpk(e1);
            *reinterpret_cast<float4*>(out + (size_t)(gr + 2) * DDIM + dcol) =
                make_float4(lo.x, lo.y, hi.x, hi.y);
        }
        if (gr + 3 < nRows) {
            lo = unpk(f0); hi = unpk(f1);
            *reinterpret_cast<float4*>(out + (size_t)(gr + 3) * DDIM + dcol) =
                make_float4(lo.x, lo.y, hi.x, hi.y);
        }
    }
}

extern "C" void kernel_launch(void* const* d_in, const int* in_sizes, int n_in,
                              void* d_out, int out_size) {
    const float* x     = (const float*)d_in[0];
    const float* W1    = (const float*)d_in[1];
    const float* b1    = (const float*)d_in[2];
    const float* theta = (const float*)d_in[3];
    const float* W2    = (const float*)d_in[4];
    const float* b2    = (const float*)d_in[5];
    float* out = (float*)d_out;

    int nRows = in_sizes[0] / DDIM;                    // 32768
    int grid  = (nRows + ROWS - 1) / ROWS;             // 256

    size_t smem = (size_t)(DDIM * QDIM + 2 * ROWS * BSTR + ROWS * ZSTR + 2 * QDIM)
                  * sizeof(float);                     // ~104.8 KB
    static int attr_set = 0;
    if (!attr_set) {
        cudaFuncSetAttribute(ffq_v5, cudaFuncAttributeMaxDynamicSharedMemorySize,
                             (int)smem);
        attr_set = 1;
    }

    ffq_v5<<<grid, NTH, smem>>>(x, W1, b1, theta, W2, b2, out, nRows);
}